// round 14
// baseline (speedup 1.0000x reference)
#include <cuda_runtime.h>
#include <cuda_fp16.h>
#include <cstdint>

// ConvTranspose2d (k==s==2) == GEMM: M=32768 pixels, N=1024 (o*4+i*2+j), K=512 (c)
// Single-pass fp16 mma (fp32 accumulate): rel_err ~2.8e-4 < 1e-3 gate (measured).
// Phase 1: transpose+convert, fully vectorized + XOR-swizzled smem (uint4 both
//          directions, zero bank conflicts): x -> g_xF [32768][512] fp16 (one
//          launch, z=batch), w -> g_wF [1024][512] fp16.
// Phase 2: mma.sync fp16 GEMM — R8 mainloop + __stcs epilogue (measured best:
//          256 thr / 8 warps (4Mx2N), warp tile 32x64, 2 CTAs/SM, BK=64,
//          3-stage cp.async, 1 sync/iter).

#define M_TOTAL 32768
#define K_TOTAL 512
#define N_TOTAL 1024
#define BM 128
#define BN 128
#define BK 64
#define KITERS (K_TOTAL / BK)
#define ROWB 128                       // bytes per smem row (64 fp16)
#define STAGE_BYTES (2 * 128 * ROWB)   // A 16KB + B 16KB
#define NSTAGE 3
#define SMEM_TOTAL (NSTAGE * STAGE_BYTES)   // 96KB -> 2 CTAs/SM

// -------- device scratch (allocation-free rule: __device__ globals) --------
__device__ __half g_xF[(size_t)M_TOTAL * K_TOTAL];   // [p][c]
__device__ __half g_wF[(size_t)N_TOTAL * K_TOTAL];   // [n][k]

// ---------------- helpers ----------------
__device__ __forceinline__ uint32_t smem_u32(const void* p) {
    uint32_t a;
    asm("{ .reg .u64 t; cvta.to.shared.u64 t, %1; cvt.u32.u64 %0, t; }" : "=r"(a) : "l"(p));
    return a;
}

#define CP_ASYNC16(dst, src) \
    asm volatile("cp.async.cg.shared.global [%0], [%1], 16;" :: "r"(dst), "l"(src) : "memory")
#define CP_COMMIT()  asm volatile("cp.async.commit_group;" ::: "memory")
#define CP_WAIT1()   asm volatile("cp.async.wait_group 1;" ::: "memory")
#define CP_WAIT0()   asm volatile("cp.async.wait_group 0;" ::: "memory")

#define LDMX4(R, addr)                                                          \
    asm volatile("ldmatrix.sync.aligned.m8n8.x4.shared.b16 {%0,%1,%2,%3}, [%4];"\
        : "=r"((R)[0]), "=r"((R)[1]), "=r"((R)[2]), "=r"((R)[3]) : "r"(addr))

#define MMA16816(ACC, A, B)                                                     \
    asm volatile("mma.sync.aligned.m16n8k16.row.col.f32.f16.f16.f32 "           \
        "{%0,%1,%2,%3}, {%4,%5,%6,%7}, {%8,%9}, {%0,%1,%2,%3};"                 \
        : "+f"((ACC)[0]), "+f"((ACC)[1]), "+f"((ACC)[2]), "+f"((ACC)[3])        \
        : "r"((A)[0]), "r"((A)[1]), "r"((A)[2]), "r"((A)[3]),                   \
          "r"((B)[0]), "r"((B)[1]))

// ---------------- Phase 1: transpose + fp16 convert (vectorized, swizzled) ----
// src: [z][R][C] fp32 -> dst: [z][C][R] fp16.  Tile: 128 c-rows x 64 p-cols,
// 256 threads. SMEM = uint4[128][16], logical chunk c4 of row r stored at
// physical chunk (c4 ^ (r & 15)) -> conflict-free LDS.128/STS.128 both ways.
// Each thread: 8 float4 gmem loads, 8 STS.128, 8 LDS.128 (a 4p x 8c block),
// register transpose + cvt, 4 x 16B gmem stores (lane pairs form 32B sectors).
__global__ __launch_bounds__(256)
void tsplit_kernel(const float* __restrict__ src,
                   __half* __restrict__ dst,
                   int R, int C)
{
    __shared__ uint4 tile[128][16];
    int b = blockIdx.z;
    src += (size_t)b * R * C;
    dst += (size_t)b * R * C;
    int p0 = blockIdx.x * 64;
    int c0 = blockIdx.y * 128;
    int tid = threadIdx.x;

    // ---- load: rows = c (128), 16 float4 chunks of p per row ----
    #pragma unroll
    for (int i = 0; i < 8; i++) {            // 2048 chunks
        int q = tid + i * 256;
        int r = q >> 4;                      // c-row 0..127
        int c4 = q & 15;                     // float4 chunk 0..15
        const float4* s = (const float4*)(src + (size_t)(c0 + r) * C + p0 + c4 * 4);
        tile[r][c4 ^ (r & 15)] = *(const uint4*)s;
    }
    __syncthreads();

    // ---- store: thread handles 4p x 8c block (pb = p-block, cb = c-block) ----
    {
        int pb = tid & 15;                   // p-block 0..15 (4 p each)
        int cb = tid >> 4;                   // c-block 0..15 (8 c each)
        float4 v[8];
        #pragma unroll
        for (int k = 0; k < 8; k++) {
            int row = cb * 8 + k;
            uint4 u = tile[row][pb ^ (row & 15)];
            v[k] = *(float4*)&u;
        }
        const float* vf = (const float*)v;   // vf[k*4 + p_inner]
        #pragma unroll
        for (int pi = 0; pi < 4; pi++) {
            __half2 h0 = __floats2half2_rn(vf[0 * 4 + pi], vf[1 * 4 + pi]);
            __half2 h1 = __floats2half2_rn(vf[2 * 4 + pi], vf[3 * 4 + pi]);
            __half2 h2 = __floats2half2_rn(vf[4 * 4 + pi], vf[5 * 4 + pi]);
            __half2 h3 = __floats2half2_rn(vf[6 * 4 + pi], vf[7 * 4 + pi]);
            uint4 st;
            st.x = *(uint32_t*)&h0;
            st.y = *(uint32_t*)&h1;
            st.z = *(uint32_t*)&h2;
            st.w = *(uint32_t*)&h3;
            *(uint4*)(dst + (size_t)(p0 + pb * 4 + pi) * R + c0 + cb * 8) = st;
        }
    }
}

// ---------------- Phase 2: mma.sync fp16 GEMM (R8 mainloop + stcs) ----------------
// SMEM stage: A = 128 rows x 128B, B = 128 rows x 128B.
// Row r, 16B chunk c stored at ((c ^ (r&7))<<4): conflict-free for cp.async
// stores and all ldmatrix phases.

__global__ __launch_bounds__(256, 2)
void gemm_mma_kernel(const float* __restrict__ bias, float* __restrict__ out)
{
    extern __shared__ char smem[];
    const uint32_t sbase = smem_u32(smem);

    const int tid  = threadIdx.x;
    const int lane = tid & 31;
    const int warp = tid >> 5;
    const int g    = lane >> 2;       // mma row within fragment
    const int tg   = lane & 3;        // mma col-pair selector
    const int wm   = warp & 3;        // 4 warps along M (32 rows each)
    const int wn   = warp >> 2;       // 2 warps along N (64 cols each)

    const int nb = blockIdx.x;        // 0..7   (N tile of 128)
    const int mb = blockIdx.y;        // 0..255 (M tile of 128)

    const __half* gA = g_xF + (size_t)mb * BM * K_TOTAL;
    const __half* gB = g_wF + (size_t)nb * BN * K_TOTAL;

    // ldmatrix per-lane addressing
    const int x7   = lane & 7;
    const int rA   = x7 + ((lane >> 3) & 1) * 8;          // row-in-16, A x4
    const int selA = lane >> 4;                           // k8 select, A x4
    const int rB   = ((lane >> 4) << 3) + x7;             // row-in-16, B x4 (nt pair)
    const int selB = (lane >> 3) & 1;                     // k8 select, B x4
    const uint32_t aBase = (uint32_t)(wm * 32 + rA) * ROWB;
    const uint32_t bBase = (uint32_t)(wn * 64 + rB) * ROWB;

    float acc[2][8][4];
    #pragma unroll
    for (int i = 0; i < 2; i++)
        #pragma unroll
        for (int j = 0; j < 8; j++)
            #pragma unroll
            for (int r = 0; r < 4; r++) acc[i][j][r] = 0.f;

    // ---- async staging of one k-stage (BK=64) into stage buffer ----
    auto stage_load = [&](int it, int buf) {
        const int k0 = it * BK;
        const uint32_t sA = sbase + buf * STAGE_BYTES;
        const uint32_t sB = sA + 128 * ROWB;
        #pragma unroll
        for (int i = 0; i < 4; i++) {                 // A: 1024 x 16B chunks
            int q = tid + i * 256;
            int r = q >> 3, c = q & 7;
            CP_ASYNC16(sA + (uint32_t)r * ROWB + (uint32_t)((c ^ (r & 7)) << 4),
                       gA + (size_t)r * K_TOTAL + k0 + c * 8);
        }
        #pragma unroll
        for (int i = 0; i < 4; i++) {                 // B: 1024 x 16B chunks
            int q = tid + i * 256;
            int r = q >> 3, c = q & 7;
            CP_ASYNC16(sB + (uint32_t)r * ROWB + (uint32_t)((c ^ (r & 7)) << 4),
                       gB + (size_t)r * K_TOTAL + k0 + c * 8);
        }
    };

    // prologue: two stages in flight
    stage_load(0, 0);
    CP_COMMIT();
    stage_load(1, 1);
    CP_COMMIT();

    for (int it = 0; it < KITERS; it++) {
        if (it + 1 < KITERS) { CP_WAIT1(); } else { CP_WAIT0(); }
        __syncthreads();          // releases compute(it) + certifies (it+2)%3 buffer
        if (it + 2 < KITERS) {
            stage_load(it + 2, (it + 2) % NSTAGE);
            CP_COMMIT();
        }

        const uint32_t sA = sbase + (it % NSTAGE) * STAGE_BYTES;
        const uint32_t sB = sA + 128 * ROWB;

        #pragma unroll
        for (int kc = 0; kc < 4; kc++) {              // four k16 chunks in BK=64
            uint32_t a[8], b[16];
            #pragma unroll
            for (int mt = 0; mt < 2; mt++)
                LDMX4(a + mt * 4, sA + aBase + (uint32_t)mt * 16 * ROWB
                                  + (uint32_t)(((kc * 2 + selA) ^ x7) << 4));
            #pragma unroll
            for (int ntp = 0; ntp < 4; ntp++)         // each LDMX4 covers 2 nt
                LDMX4(b + ntp * 4, sB + bBase + (uint32_t)ntp * 16 * ROWB
                                   + (uint32_t)(((kc * 2 + selB) ^ x7) << 4));
            #pragma unroll
            for (int mt = 0; mt < 2; mt++)
                #pragma unroll
                for (int nt = 0; nt < 8; nt++)
                    MMA16816(acc[mt][nt], a + mt * 4, b + nt * 2);
        }
    }

    // ---- epilogue: scatter to out[b][o][2h+i][2w+j], fused bias, streaming ----
    #pragma unroll
    for (int mt = 0; mt < 2; mt++) {
        int r0 = mb * 128 + wm * 32 + mt * 16 + g;
        #pragma unroll
        for (int half = 0; half < 2; half++) {
            int p  = r0 + half * 8;
            int bb = p >> 12;
            int h  = (p >> 6) & 63;
            int wp = p & 63;
            #pragma unroll
            for (int nt = 0; nt < 8; nt++) {
                int n  = nb * 128 + wn * 64 + nt * 8 + tg * 2;   // even -> (j=0, j=1)
                int o  = n >> 2;
                int ii = (n >> 1) & 1;
                float bo = __ldg(bias + o);
                size_t addr = (((size_t)(bb * 256 + o) * 128) + (h * 2 + ii)) * 128 + wp * 2;
                float2 v;
                v.x = acc[mt][nt][half * 2 + 0] + bo;
                v.y = acc[mt][nt][half * 2 + 1] + bo;
                __stcs((float2*)(out + addr), v);
            }
        }
    }
}

// ---------------- launch ----------------
extern "C" void kernel_launch(void* const* d_in, const int* in_sizes, int n_in,
                              void* d_out, int out_size)
{
    const float* x    = (const float*)d_in[0];   // [8,512,64,64]
    const float* wgt  = (const float*)d_in[1];   // [512,256,2,2] -> [512][1024]
    const float* bias = (const float*)d_in[2];   // [256]
    float* out = (float*)d_out;                  // [8,256,128,128]

    void *pxF, *pwF;
    cudaGetSymbolAddress(&pxF, g_xF);
    cudaGetSymbolAddress(&pwF, g_wF);
    __half* xF = (__half*)pxF;
    __half* wF = (__half*)pwF;

    // Phase 1: x transpose in ONE launch (z = batch); then tiny w transpose.
    tsplit_kernel<<<dim3(4096 / 64, 512 / 128, 8), 256>>>(x, xF, 512, 4096);
    tsplit_kernel<<<dim3(1024 / 64, 512 / 128, 1), 256>>>(wgt, wF, 512, 1024);

    // Phase 2
    static int attr_set = 0;
    if (!attr_set) {
        cudaFuncSetAttribute(gemm_mma_kernel,
                             cudaFuncAttributeMaxDynamicSharedMemorySize, SMEM_TOTAL);
        attr_set = 1;
    }
    dim3 grid(N_TOTAL / BN, M_TOTAL / BM);   // (8, 256) — nb fastest for A-tile L2 reuse
    gemm_mma_kernel<<<grid, 256, SMEM_TOTAL>>>(bias, out);
}

// round 15
// speedup vs baseline: 1.0185x; 1.0185x over previous
#include <cuda_runtime.h>
#include <cuda_fp16.h>
#include <cstdint>

// ConvTranspose2d (k==s==2) == GEMM: M=32768 pixels, N=1024 (o*4+i*2+j), K=512 (c)
// Single-pass fp16 mma (fp32 accumulate): rel_err ~2.8e-4 < 1e-3 gate (measured).
// Phase 1: transpose+convert (R13 measured-best config: 64x64 tiles, float4
//          loads, uint4 stores, one launch with z=batch).
// Phase 2: mma.sync fp16 GEMM — R8 mainloop + __stcs epilogue + hoisted bias
//          (256 thr / 8 warps (4Mx2N), warp tile 32x64, 2 CTAs/SM, BK=64,
//          3-stage cp.async, 1 sync/iter).

#define M_TOTAL 32768
#define K_TOTAL 512
#define N_TOTAL 1024
#define BM 128
#define BN 128
#define BK 64
#define KITERS (K_TOTAL / BK)
#define ROWB 128                       // bytes per smem row (64 fp16)
#define STAGE_BYTES (2 * 128 * ROWB)   // A 16KB + B 16KB
#define NSTAGE 3
#define SMEM_TOTAL (NSTAGE * STAGE_BYTES)   // 96KB -> 2 CTAs/SM

// -------- device scratch (allocation-free rule: __device__ globals) --------
__device__ __half g_xF[(size_t)M_TOTAL * K_TOTAL];   // [p][c]
__device__ __half g_wF[(size_t)N_TOTAL * K_TOTAL];   // [n][k]

// ---------------- helpers ----------------
__device__ __forceinline__ uint32_t smem_u32(const void* p) {
    uint32_t a;
    asm("{ .reg .u64 t; cvta.to.shared.u64 t, %1; cvt.u32.u64 %0, t; }" : "=r"(a) : "l"(p));
    return a;
}

#define CP_ASYNC16(dst, src) \
    asm volatile("cp.async.cg.shared.global [%0], [%1], 16;" :: "r"(dst), "l"(src) : "memory")
#define CP_COMMIT()  asm volatile("cp.async.commit_group;" ::: "memory")
#define CP_WAIT1()   asm volatile("cp.async.wait_group 1;" ::: "memory")
#define CP_WAIT0()   asm volatile("cp.async.wait_group 0;" ::: "memory")

#define LDMX4(R, addr)                                                          \
    asm volatile("ldmatrix.sync.aligned.m8n8.x4.shared.b16 {%0,%1,%2,%3}, [%4];"\
        : "=r"((R)[0]), "=r"((R)[1]), "=r"((R)[2]), "=r"((R)[3]) : "r"(addr))

#define MMA16816(ACC, A, B)                                                     \
    asm volatile("mma.sync.aligned.m16n8k16.row.col.f32.f16.f16.f32 "           \
        "{%0,%1,%2,%3}, {%4,%5,%6,%7}, {%8,%9}, {%0,%1,%2,%3};"                 \
        : "+f"((ACC)[0]), "+f"((ACC)[1]), "+f"((ACC)[2]), "+f"((ACC)[3])        \
        : "r"((A)[0]), "r"((A)[1]), "r"((A)[2]), "r"((A)[3]),                   \
          "r"((B)[0]), "r"((B)[1]))

// ---------------- Phase 1: transpose + fp16 convert (R13 config) ----------------
// src: [z][R][C] fp32 -> dst: [z][C][R] fp16.  64x64 tile, 256 threads.
// Load: 1024 float4 (4/thread), coalesced 128B lines.
// Store: 512 uint4 (2/thread); each 8-lane group writes one full 128B dst row.
__global__ __launch_bounds__(256)
void tsplit_kernel(const float* __restrict__ src,
                   __half* __restrict__ dst,
                   int R, int C)
{
    __shared__ float tile[64][65];
    int b = blockIdx.z;
    src += (size_t)b * R * C;
    dst += (size_t)b * R * C;
    int p0 = blockIdx.x * 64;
    int c0 = blockIdx.y * 64;
    int tid = threadIdx.x;

    #pragma unroll
    for (int i = 0; i < 4; i++) {            // 1024 float4 chunks
        int q = tid + i * 256;
        int r = q >> 4;                      // c-row 0..63
        int c4 = q & 15;                     // float4 col 0..15
        float4 v = *(const float4*)(src + (size_t)(c0 + r) * C + p0 + c4 * 4);
        tile[r][c4 * 4 + 0] = v.x;
        tile[r][c4 * 4 + 1] = v.y;
        tile[r][c4 * 4 + 2] = v.z;
        tile[r][c4 * 4 + 3] = v.w;
    }
    __syncthreads();

    #pragma unroll
    for (int i = 0; i < 2; i++) {            // 512 uint4 chunks
        int q = tid + i * 256;
        int pr = q >> 3;                     // p-row 0..63
        int c8 = q & 7;                      // 8-channel group 0..7
        // hoist all 16 smem reads ahead of the convert chain (ILP)
        float v[16];
        #pragma unroll
        for (int j = 0; j < 16; j++)
            v[j] = tile[c8 * 8 + j % 8 + (j / 8) * 0][pr];   // placeholder ordering
        #pragma unroll
        for (int j = 0; j < 8; j++)
            v[j] = tile[c8 * 8 + j][pr];
        __half2 h[4];
        #pragma unroll
        for (int j = 0; j < 4; j++)
            h[j] = __floats2half2_rn(v[j * 2], v[j * 2 + 1]);
        uint4 st;
        st.x = *(uint32_t*)&h[0];
        st.y = *(uint32_t*)&h[1];
        st.z = *(uint32_t*)&h[2];
        st.w = *(uint32_t*)&h[3];
        *(uint4*)(dst + (size_t)(p0 + pr) * R + c0 + c8 * 8) = st;
    }
}

// ---------------- Phase 2: mma.sync fp16 GEMM (R8 mainloop + stcs) ----------------
// SMEM stage: A = 128 rows x 128B, B = 128 rows x 128B.
// Row r, 16B chunk c stored at ((c ^ (r&7))<<4): conflict-free for cp.async
// stores and all ldmatrix phases.

__global__ __launch_bounds__(256, 2)
void gemm_mma_kernel(const float* __restrict__ bias, float* __restrict__ out)
{
    extern __shared__ char smem[];
    const uint32_t sbase = smem_u32(smem);

    const int tid  = threadIdx.x;
    const int lane = tid & 31;
    const int warp = tid >> 5;
    const int g    = lane >> 2;       // mma row within fragment
    const int tg   = lane & 3;        // mma col-pair selector
    const int wm   = warp & 3;        // 4 warps along M (32 rows each)
    const int wn   = warp >> 2;       // 2 warps along N (64 cols each)

    const int nb = blockIdx.x;        // 0..7   (N tile of 128)
    const int mb = blockIdx.y;        // 0..255 (M tile of 128)

    const __half* gA = g_xF + (size_t)mb * BM * K_TOTAL;
    const __half* gB = g_wF + (size_t)nb * BN * K_TOTAL;

    // ldmatrix per-lane addressing
    const int x7   = lane & 7;
    const int rA   = x7 + ((lane >> 3) & 1) * 8;          // row-in-16, A x4
    const int selA = lane >> 4;                           // k8 select, A x4
    const int rB   = ((lane >> 4) << 3) + x7;             // row-in-16, B x4 (nt pair)
    const int selB = (lane >> 3) & 1;                     // k8 select, B x4
    const uint32_t aBase = (uint32_t)(wm * 32 + rA) * ROWB;
    const uint32_t bBase = (uint32_t)(wn * 64 + rB) * ROWB;

    float acc[2][8][4];
    #pragma unroll
    for (int i = 0; i < 2; i++)
        #pragma unroll
        for (int j = 0; j < 8; j++)
            #pragma unroll
            for (int r = 0; r < 4; r++) acc[i][j][r] = 0.f;

    // ---- async staging of one k-stage (BK=64) into stage buffer ----
    auto stage_load = [&](int it, int buf) {
        const int k0 = it * BK;
        const uint32_t sA = sbase + buf * STAGE_BYTES;
        const uint32_t sB = sA + 128 * ROWB;
        #pragma unroll
        for (int i = 0; i < 4; i++) {                 // A: 1024 x 16B chunks
            int q = tid + i * 256;
            int r = q >> 3, c = q & 7;
            CP_ASYNC16(sA + (uint32_t)r * ROWB + (uint32_t)((c ^ (r & 7)) << 4),
                       gA + (size_t)r * K_TOTAL + k0 + c * 8);
        }
        #pragma unroll
        for (int i = 0; i < 4; i++) {                 // B: 1024 x 16B chunks
            int q = tid + i * 256;
            int r = q >> 3, c = q & 7;
            CP_ASYNC16(sB + (uint32_t)r * ROWB + (uint32_t)((c ^ (r & 7)) << 4),
                       gB + (size_t)r * K_TOTAL + k0 + c * 8);
        }
    };

    // prologue: two stages in flight
    stage_load(0, 0);
    CP_COMMIT();
    stage_load(1, 1);
    CP_COMMIT();

    for (int it = 0; it < KITERS; it++) {
        if (it + 1 < KITERS) { CP_WAIT1(); } else { CP_WAIT0(); }
        __syncthreads();          // releases compute(it) + certifies (it+2)%3 buffer
        if (it + 2 < KITERS) {
            stage_load(it + 2, (it + 2) % NSTAGE);
            CP_COMMIT();
        }

        const uint32_t sA = sbase + (it % NSTAGE) * STAGE_BYTES;
        const uint32_t sB = sA + 128 * ROWB;

        #pragma unroll
        for (int kc = 0; kc < 4; kc++) {              // four k16 chunks in BK=64
            uint32_t a[8], b[16];
            #pragma unroll
            for (int mt = 0; mt < 2; mt++)
                LDMX4(a + mt * 4, sA + aBase + (uint32_t)mt * 16 * ROWB
                                  + (uint32_t)(((kc * 2 + selA) ^ x7) << 4));
            #pragma unroll
            for (int ntp = 0; ntp < 4; ntp++)         // each LDMX4 covers 2 nt
                LDMX4(b + ntp * 4, sB + bBase + (uint32_t)ntp * 16 * ROWB
                                   + (uint32_t)(((kc * 2 + selB) ^ x7) << 4));
            #pragma unroll
            for (int mt = 0; mt < 2; mt++)
                #pragma unroll
                for (int nt = 0; nt < 8; nt++)
                    MMA16816(acc[mt][nt], a + mt * 4, b + nt * 2);
        }
    }

    // ---- epilogue: hoist bias (8 distinct o per thread), then scatter ----
    float bo[8];
    #pragma unroll
    for (int nt = 0; nt < 8; nt++) {
        int n = nb * 128 + wn * 64 + nt * 8 + tg * 2;
        bo[nt] = __ldg(bias + (n >> 2));
    }

    #pragma unroll
    for (int mt = 0; mt < 2; mt++) {
        int r0 = mb * 128 + wm * 32 + mt * 16 + g;
        #pragma unroll
        for (int half = 0; half < 2; half++) {
            int p  = r0 + half * 8;
            int bb = p >> 12;
            int h  = (p >> 6) & 63;
            int wp = p & 63;
            #pragma unroll
            for (int nt = 0; nt < 8; nt++) {
                int n  = nb * 128 + wn * 64 + nt * 8 + tg * 2;   // even -> (j=0, j=1)
                int o  = n >> 2;
                int ii = (n >> 1) & 1;
                size_t addr = (((size_t)(bb * 256 + o) * 128) + (h * 2 + ii)) * 128 + wp * 2;
                float2 v;
                v.x = acc[mt][nt][half * 2 + 0] + bo[nt];
                v.y = acc[mt][nt][half * 2 + 1] + bo[nt];
                __stcs((float2*)(out + addr), v);
            }
        }
    }
}

// ---------------- launch ----------------
extern "C" void kernel_launch(void* const* d_in, const int* in_sizes, int n_in,
                              void* d_out, int out_size)
{
    const float* x    = (const float*)d_in[0];   // [8,512,64,64]
    const float* wgt  = (const float*)d_in[1];   // [512,256,2,2] -> [512][1024]
    const float* bias = (const float*)d_in[2];   // [256]
    float* out = (float*)d_out;                  // [8,256,128,128]

    void *pxF, *pwF;
    cudaGetSymbolAddress(&pxF, g_xF);
    cudaGetSymbolAddress(&pwF, g_wF);
    __half* xF = (__half*)pxF;
    __half* wF = (__half*)pwF;

    // Phase 1: x transpose in ONE launch (z = batch); then tiny w transpose.
    tsplit_kernel<<<dim3(4096 / 64, 512 / 64, 8), 256>>>(x, xF, 512, 4096);
    tsplit_kernel<<<dim3(1024 / 64, 512 / 64, 1), 256>>>(wgt, wF, 512, 1024);

    // Phase 2
    static int attr_set = 0;
    if (!attr_set) {
        cudaFuncSetAttribute(gemm_mma_kernel,
                             cudaFuncAttributeMaxDynamicSharedMemorySize, SMEM_TOTAL);
        attr_set = 1;
    }
    dim3 grid(N_TOTAL / BN, M_TOTAL / BM);   // (8, 256) — nb fastest for A-tile L2 reuse
    gemm_mma_kernel<<<grid, 256, SMEM_TOTAL>>>(bias, out);
}

// round 17
// speedup vs baseline: 1.0758x; 1.0563x over previous
#include <cuda_runtime.h>
#include <cuda_fp16.h>
#include <cstdint>

// ConvTranspose2d (k==s==2) == GEMM: M=32768 pixels, N=1024 (o*4+i*2+j), K=512 (c)
// Single-pass fp16 mma (fp32 accumulate): rel_err ~2.8e-4 < 1e-3 gate (measured).
// Phase 1: ONE launch transposes+converts BOTH tensors (z=0..7: x batches,
//          z=8: w, 128 tiles). R13 measured-best tile config: 64x64, float4
//          loads, uint4 stores.
// Phase 2: mma.sync fp16 GEMM — R13-exact mainloop + epilogue (256 thr /
//          8 warps (4Mx2N), warp tile 32x64, 2 CTAs/SM, BK=64, 3-stage
//          cp.async, 1 sync/iter, __stcs stores).

#define M_TOTAL 32768
#define K_TOTAL 512
#define N_TOTAL 1024
#define BM 128
#define BN 128
#define BK 64
#define KITERS (K_TOTAL / BK)
#define ROWB 128                       // bytes per smem row (64 fp16)
#define STAGE_BYTES (2 * 128 * ROWB)   // A 16KB + B 16KB
#define NSTAGE 3
#define SMEM_TOTAL (NSTAGE * STAGE_BYTES)   // 96KB -> 2 CTAs/SM

// -------- device scratch (allocation-free rule: __device__ globals) --------
__device__ __half g_xF[(size_t)M_TOTAL * K_TOTAL];   // [p][c]
__device__ __half g_wF[(size_t)N_TOTAL * K_TOTAL];   // [n][k]

// ---------------- helpers ----------------
__device__ __forceinline__ uint32_t smem_u32(const void* p) {
    uint32_t a;
    asm("{ .reg .u64 t; cvta.to.shared.u64 t, %1; cvt.u32.u64 %0, t; }" : "=r"(a) : "l"(p));
    return a;
}

#define CP_ASYNC16(dst, src) \
    asm volatile("cp.async.cg.shared.global [%0], [%1], 16;" :: "r"(dst), "l"(src) : "memory")
#define CP_COMMIT()  asm volatile("cp.async.commit_group;" ::: "memory")
#define CP_WAIT1()   asm volatile("cp.async.wait_group 1;" ::: "memory")
#define CP_WAIT0()   asm volatile("cp.async.wait_group 0;" ::: "memory")

#define LDMX4(R, addr)                                                          \
    asm volatile("ldmatrix.sync.aligned.m8n8.x4.shared.b16 {%0,%1,%2,%3}, [%4];"\
        : "=r"((R)[0]), "=r"((R)[1]), "=r"((R)[2]), "=r"((R)[3]) : "r"(addr))

#define MMA16816(ACC, A, B)                                                     \
    asm volatile("mma.sync.aligned.m16n8k16.row.col.f32.f16.f16.f32 "           \
        "{%0,%1,%2,%3}, {%4,%5,%6,%7}, {%8,%9}, {%0,%1,%2,%3};"                 \
        : "+f"((ACC)[0]), "+f"((ACC)[1]), "+f"((ACC)[2]), "+f"((ACC)[3])        \
        : "r"((A)[0]), "r"((A)[1]), "r"((A)[2]), "r"((A)[3]),                   \
          "r"((B)[0]), "r"((B)[1]))

// ---------------- Phase 1: fused transpose + fp16 convert (x AND w) ----------------
// z = 0..7: x batch z, [512][4096] -> [4096][512] (64 x 8 tiles).
// z = 8   : w, [512][1024] -> [1024][512] (16 p-tiles x 8 c-tiles = 128 tiles,
//           linearized over the 512 block slots; slots >= 128 exit).
// 64x64 tile, 256 threads. Load: 1024 float4 (4/thread), coalesced 128B lines.
// Store: 512 uint4 (2/thread); each 8-lane group writes one full 128B dst row.
__global__ __launch_bounds__(256)
void tsplit_kernel(const float* __restrict__ x, __half* __restrict__ xF,
                   const float* __restrict__ w, __half* __restrict__ wF)
{
    __shared__ float tile[64][65];
    const int R = 512;
    const float* src;
    __half* dst;
    int C, p0, c0;

    if (blockIdx.z < 8) {                    // x slice
        int b = blockIdx.z;
        src = x  + (size_t)b * R * 4096;
        dst = xF + (size_t)b * 4096 * R;
        C = 4096;
        p0 = blockIdx.x * 64;
        c0 = blockIdx.y * 64;
    } else {                                 // w slice: 128 tiles (16 p x 8 c)
        int q = blockIdx.x + 64 * blockIdx.y;
        if (q >= 128) return;
        src = w;
        dst = wF;
        C = 1024;
        p0 = (q & 15) * 64;                  // 16 p-tiles
        c0 = (q >> 4) * 64;                  // 8 c-tiles
    }

    int tid = threadIdx.x;

    #pragma unroll
    for (int i = 0; i < 4; i++) {            // 1024 float4 chunks
        int q = tid + i * 256;
        int r = q >> 4;                      // c-row 0..63
        int c4 = q & 15;                     // float4 col 0..15
        float4 v = *(const float4*)(src + (size_t)(c0 + r) * C + p0 + c4 * 4);
        tile[r][c4 * 4 + 0] = v.x;
        tile[r][c4 * 4 + 1] = v.y;
        tile[r][c4 * 4 + 2] = v.z;
        tile[r][c4 * 4 + 3] = v.w;
    }
    __syncthreads();

    #pragma unroll
    for (int i = 0; i < 2; i++) {            // 512 uint4 chunks
        int q = tid + i * 256;
        int pr = q >> 3;                     // p-row 0..63
        int c8 = q & 7;                      // 8-channel group 0..7
        __half2 h[4];
        #pragma unroll
        for (int j = 0; j < 4; j++)
            h[j] = __floats2half2_rn(tile[c8 * 8 + j * 2][pr],
                                     tile[c8 * 8 + j * 2 + 1][pr]);
        uint4 st;
        st.x = *(uint32_t*)&h[0];
        st.y = *(uint32_t*)&h[1];
        st.z = *(uint32_t*)&h[2];
        st.w = *(uint32_t*)&h[3];
        *(uint4*)(dst + (size_t)(p0 + pr) * R + c0 + c8 * 8) = st;
    }
}

// ---------------- Phase 2: mma.sync fp16 GEMM (R13-exact) ----------------
// SMEM stage: A = 128 rows x 128B, B = 128 rows x 128B.
// Row r, 16B chunk c stored at ((c ^ (r&7))<<4): conflict-free for cp.async
// stores and all ldmatrix phases.

__global__ __launch_bounds__(256, 2)
void gemm_mma_kernel(const float* __restrict__ bias, float* __restrict__ out)
{
    extern __shared__ char smem[];
    const uint32_t sbase = smem_u32(smem);

    const int tid  = threadIdx.x;
    const int lane = tid & 31;
    const int warp = tid >> 5;
    const int g    = lane >> 2;       // mma row within fragment
    const int tg   = lane & 3;        // mma col-pair selector
    const int wm   = warp & 3;        // 4 warps along M (32 rows each)
    const int wn   = warp >> 2;       // 2 warps along N (64 cols each)

    const int nb = blockIdx.x;        // 0..7   (N tile of 128)
    const int mb = blockIdx.y;        // 0..255 (M tile of 128)

    const __half* gA = g_xF + (size_t)mb * BM * K_TOTAL;
    const __half* gB = g_wF + (size_t)nb * BN * K_TOTAL;

    // ldmatrix per-lane addressing
    const int x7   = lane & 7;
    const int rA   = x7 + ((lane >> 3) & 1) * 8;          // row-in-16, A x4
    const int selA = lane >> 4;                           // k8 select, A x4
    const int rB   = ((lane >> 4) << 3) + x7;             // row-in-16, B x4 (nt pair)
    const int selB = (lane >> 3) & 1;                     // k8 select, B x4
    const uint32_t aBase = (uint32_t)(wm * 32 + rA) * ROWB;
    const uint32_t bBase = (uint32_t)(wn * 64 + rB) * ROWB;

    float acc[2][8][4];
    #pragma unroll
    for (int i = 0; i < 2; i++)
        #pragma unroll
        for (int j = 0; j < 8; j++)
            #pragma unroll
            for (int r = 0; r < 4; r++) acc[i][j][r] = 0.f;

    // ---- async staging of one k-stage (BK=64) into stage buffer ----
    auto stage_load = [&](int it, int buf) {
        const int k0 = it * BK;
        const uint32_t sA = sbase + buf * STAGE_BYTES;
        const uint32_t sB = sA + 128 * ROWB;
        #pragma unroll
        for (int i = 0; i < 4; i++) {                 // A: 1024 x 16B chunks
            int q = tid + i * 256;
            int r = q >> 3, c = q & 7;
            CP_ASYNC16(sA + (uint32_t)r * ROWB + (uint32_t)((c ^ (r & 7)) << 4),
                       gA + (size_t)r * K_TOTAL + k0 + c * 8);
        }
        #pragma unroll
        for (int i = 0; i < 4; i++) {                 // B: 1024 x 16B chunks
            int q = tid + i * 256;
            int r = q >> 3, c = q & 7;
            CP_ASYNC16(sB + (uint32_t)r * ROWB + (uint32_t)((c ^ (r & 7)) << 4),
                       gB + (size_t)r * K_TOTAL + k0 + c * 8);
        }
    };

    // prologue: two stages in flight
    stage_load(0, 0);
    CP_COMMIT();
    stage_load(1, 1);
    CP_COMMIT();

    for (int it = 0; it < KITERS; it++) {
        if (it + 1 < KITERS) { CP_WAIT1(); } else { CP_WAIT0(); }
        __syncthreads();          // releases compute(it) + certifies (it+2)%3 buffer
        if (it + 2 < KITERS) {
            stage_load(it + 2, (it + 2) % NSTAGE);
            CP_COMMIT();
        }

        const uint32_t sA = sbase + (it % NSTAGE) * STAGE_BYTES;
        const uint32_t sB = sA + 128 * ROWB;

        #pragma unroll
        for (int kc = 0; kc < 4; kc++) {              // four k16 chunks in BK=64
            uint32_t a[8], b[16];
            #pragma unroll
            for (int mt = 0; mt < 2; mt++)
                LDMX4(a + mt * 4, sA + aBase + (uint32_t)mt * 16 * ROWB
                                  + (uint32_t)(((kc * 2 + selA) ^ x7) << 4));
            #pragma unroll
            for (int ntp = 0; ntp < 4; ntp++)         // each LDMX4 covers 2 nt
                LDMX4(b + ntp * 4, sB + bBase + (uint32_t)ntp * 16 * ROWB
                                   + (uint32_t)(((kc * 2 + selB) ^ x7) << 4));
            #pragma unroll
            for (int mt = 0; mt < 2; mt++)
                #pragma unroll
                for (int nt = 0; nt < 8; nt++)
                    MMA16816(acc[mt][nt], a + mt * 4, b + nt * 2);
        }
    }

    // ---- epilogue: scatter to out[b][o][2h+i][2w+j], fused bias, streaming ----
    #pragma unroll
    for (int mt = 0; mt < 2; mt++) {
        int r0 = mb * 128 + wm * 32 + mt * 16 + g;
        #pragma unroll
        for (int half = 0; half < 2; half++) {
            int p  = r0 + half * 8;
            int bb = p >> 12;
            int h  = (p >> 6) & 63;
            int wp = p & 63;
            #pragma unroll
            for (int nt = 0; nt < 8; nt++) {
                int n  = nb * 128 + wn * 64 + nt * 8 + tg * 2;   // even -> (j=0, j=1)
                int o  = n >> 2;
                int ii = (n >> 1) & 1;
                float bo = __ldg(bias + o);
                size_t addr = (((size_t)(bb * 256 + o) * 128) + (h * 2 + ii)) * 128 + wp * 2;
                float2 v;
                v.x = acc[mt][nt][half * 2 + 0] + bo;
                v.y = acc[mt][nt][half * 2 + 1] + bo;
                __stcs((float2*)(out + addr), v);
            }
        }
    }
}

// ---------------- launch ----------------
extern "C" void kernel_launch(void* const* d_in, const int* in_sizes, int n_in,
                              void* d_out, int out_size)
{
    const float* x    = (const float*)d_in[0];   // [8,512,64,64]
    const float* wgt  = (const float*)d_in[1];   // [512,256,2,2] -> [512][1024]
    const float* bias = (const float*)d_in[2];   // [256]
    float* out = (float*)d_out;                  // [8,256,128,128]

    void *pxF, *pwF;
    cudaGetSymbolAddress(&pxF, g_xF);
    cudaGetSymbolAddress(&pwF, g_wF);
    __half* xF = (__half*)pxF;
    __half* wF = (__half*)pwF;

    // Phase 1: ONE launch for x (z=0..7) and w (z=8, 128 active tiles).
    tsplit_kernel<<<dim3(64, 8, 9), 256>>>(x, xF, wgt, wF);

    // Phase 2
    static int attr_set = 0;
    if (!attr_set) {
        cudaFuncSetAttribute(gemm_mma_kernel,
                             cudaFuncAttributeMaxDynamicSharedMemorySize, SMEM_TOTAL);
        attr_set = 1;
    }
    dim3 grid(N_TOTAL / BN, M_TOTAL / BM);   // (8, 256) — nb fastest for A-tile L2 reuse
    gemm_mma_kernel<<<grid, 256, SMEM_TOTAL>>>(bias, out);
}